// round 10
// baseline (speedup 1.0000x reference)
#include <cuda_runtime.h>
#include <cuda_fp16.h>
#include <cstdint>
#include <stdint.h>
#include <math.h>

// Problem constants (fixed by the reference)
constexpr int NODES  = 100000;
constexpr int EDGES  = 1600000;
constexpr int GRAPHS = 64;
constexpr int DH     = 128;   // DI == DH == 128
constexpr int DOUT   = 10;

constexpr int NB      = (NODES + 255) / 256;  // alloc blocks (391)
constexpr int NTILES  = 1563;                 // 64-row GEMM tiles (1563*64 >= NODES)
constexpr int GEMM_GRID = 521;                // 1563 = 3 * 521, perfectly balanced

// Scratch (device globals: allocation-free rule)
__device__ __half  g_mh  [NODES * 128];   // messages m[i] = (h@W)*dinv[i], fp16
__device__ __half  g_aggh[NODES * 128];   // aggregate, fp16 (fp32 accum in regs)
__device__ __half  g_wh  [3 * 128 * 128]; // all 3 layers' weights, fp16, swizzled
__device__ int     g_deg [NODES];
__device__ float   g_dinv[NODES];
__device__ int     g_rowptr[NODES];       // CSR row start (end = start + deg)
__device__ int     g_cursor[NODES];
__device__ int     g_csr[EDGES];          // src indices grouped by dst
__device__ int     g_total;               // global CSR allocation cursor

// ---------------------------------------------------------------------------
// Degree
// ---------------------------------------------------------------------------
__global__ void k_zero_deg() {
    int i = blockIdx.x * blockDim.x + threadIdx.x;
    if (i < NODES) g_deg[i] = 0;
    if (i == 0) g_total = 0;
}

__global__ void k_count_deg(const int* __restrict__ ei) {   // 4 edges/thread
    int e4 = blockIdx.x * blockDim.x + threadIdx.x;
    if (e4 < EDGES / 4) {
        int4 d = ((const int4*)(ei + EDGES))[e4];
        atomicAdd(&g_deg[d.x], 1);
        atomicAdd(&g_deg[d.y], 1);
        atomicAdd(&g_deg[d.z], 1);
        atomicAdd(&g_deg[d.w], 1);
    }
}

// ---------------------------------------------------------------------------
// Fused CSR allocation + weight convert. Blocks [0,NB): block-local scan of
// degrees + one atomicAdd for the block's base (allocation order across
// blocks is arbitrary but always a valid disjoint layout) + dinv.
// Blocks [NB, NB+24): convert the 3 weight matrices fp32 -> fp16 swizzled.
// ---------------------------------------------------------------------------
__global__ void k_alloc_wconv(const float* __restrict__ W1,
                              const float* __restrict__ W2,
                              const float* __restrict__ W3) {
    if (blockIdx.x >= NB) {
        int gchunk = (blockIdx.x - NB) * 256 + threadIdx.x;   // 0..6143
        int layer = gchunk >> 11;                              // 0..2
        int chunk = gchunk & 2047;
        int row = chunk >> 4, cn = chunk & 15;
        const float* W = (layer == 0) ? W1 : (layer == 1) ? W2 : W3;
        const float4* W4 = (const float4*)W;
        float4 v0 = W4[row * 32 + cn * 2];
        float4 v1 = W4[row * 32 + cn * 2 + 1];
        union { uint4 u; __half2 h[4]; } pk;
        pk.h[0] = __floats2half2_rn(v0.x, v0.y);
        pk.h[1] = __floats2half2_rn(v0.z, v0.w);
        pk.h[2] = __floats2half2_rn(v1.x, v1.y);
        pk.h[3] = __floats2half2_rn(v1.z, v1.w);
        *(uint4*)(g_wh + layer * 128 * 128 + row * 128 + ((cn ^ (row & 7)) << 3)) = pk.u;
        return;
    }
    __shared__ int sh[256];
    __shared__ int sbase;
    int i = blockIdx.x * 256 + threadIdx.x;
    int t = threadIdx.x;
    int v = (i < NODES) ? g_deg[i] : 0;
    sh[t] = v;
    __syncthreads();
    for (int off = 1; off < 256; off <<= 1) {
        int add = (t >= off) ? sh[t - off] : 0;
        __syncthreads();
        sh[t] += add;
        __syncthreads();
    }
    if (t == 255) sbase = atomicAdd(&g_total, sh[255]);
    __syncthreads();
    if (i < NODES) {
        int start = sbase + sh[t] - v;       // exclusive within block + base
        g_rowptr[i] = start;
        g_cursor[i] = start;
        g_dinv[i] = rsqrtf((float)(v + 1));  // +1 self loop
    }
}

__global__ void k_csr_fill(const int* __restrict__ ei) {    // 4 edges/thread
    int e4 = blockIdx.x * blockDim.x + threadIdx.x;
    if (e4 < EDGES / 4) {
        int4 s = ((const int4*)ei)[e4];
        int4 d = ((const int4*)(ei + EDGES))[e4];
        g_csr[atomicAdd(&g_cursor[d.x], 1)] = s.x;
        g_csr[atomicAdd(&g_cursor[d.y], 1)] = s.y;
        g_csr[atomicAdd(&g_cursor[d.z], 1)] = s.z;
        g_csr[atomicAdd(&g_cursor[d.w], 1)] = s.w;
    }
}

// ---------------------------------------------------------------------------
// Tensor-core GEMM: m_row = (pre(in_row)) @ W * dinv[row] -> fp16 g_mh.
// pre(in) = in                      (use_pre == 0, first layer reads fp32 x)
// pre(in) = relu(in*dinv[row] + b)  (use_pre == 1, reads fp16 g_aggh)
// Persistent-ish: grid 521; each block loads sB ONCE and processes exactly
// 3 x 64-row tiles (1563 = 3*521, one balanced wave at 4 CTAs/SM).
// 8 warps, 2(m) x 4(n). XOR-swizzled smem, ldmatrix + mma.m16n8k16.
// ---------------------------------------------------------------------------
__device__ __forceinline__ uint32_t s2u(const void* p) {
    return (uint32_t)__cvta_generic_to_shared(p);
}

__global__ void __launch_bounds__(256) k_gemm_tc(const float* __restrict__ xin,
                                                 int use_pre, int wlayer,
                                                 const float* __restrict__ bias) {
    __shared__ __align__(16) __half sA[64 * 128];
    __shared__ __align__(16) __half sB[128 * 128];
    const int tid = threadIdx.x;

    // ---- B: raw copy of pre-swizzled fp16 weights (2048 x 16B), once.
    const uint4* wsrc = (const uint4*)(g_wh + wlayer * 128 * 128);
    uint4* bdst = (uint4*)sB;
#pragma unroll
    for (int i = 0; i < 8; i++) bdst[i * 256 + tid] = __ldg(wsrc + i * 256 + tid);

    const int lane = tid & 31, wid = tid >> 5;
    const int wm = wid & 1;        // 2 warps over m (32 rows each)
    const int wn = wid >> 1;       // 4 warps over n (32 cols each)
    const uint32_t sAu = s2u(sA), sBu = s2u(sB);

#pragma unroll 1
    for (int it = 0; it < 3; it++) {
        const int r0 = (blockIdx.x + it * GEMM_GRID) * 64;
        if (it) __syncthreads();       // all reads of previous sA done

        // ---- A tile [64][128] with fused pre-transform. 1024 chunks of 16B.
#pragma unroll
        for (int i = 0; i < 4; i++) {
            int chunk = i * 256 + tid;
            int row = chunk >> 4, cn = chunk & 15;
            int grow = r0 + row;
            union { uint4 u; __half2 h[4]; } pk;
            if (grow >= NODES) {
                pk.u = make_uint4(0, 0, 0, 0);
            } else if (use_pre) {
                union { uint4 u; __half2 h[4]; } in;
                in.u = *(const uint4*)(g_aggh + grow * 128 + cn * 8);
                float di = g_dinv[grow];
                const float* bp = bias + cn * 8;
                float2 f0 = __half22float2(in.h[0]);
                float2 f1 = __half22float2(in.h[1]);
                float2 f2 = __half22float2(in.h[2]);
                float2 f3 = __half22float2(in.h[3]);
                f0.x = fmaxf(fmaf(f0.x, di, bp[0]), 0.f);
                f0.y = fmaxf(fmaf(f0.y, di, bp[1]), 0.f);
                f1.x = fmaxf(fmaf(f1.x, di, bp[2]), 0.f);
                f1.y = fmaxf(fmaf(f1.y, di, bp[3]), 0.f);
                f2.x = fmaxf(fmaf(f2.x, di, bp[4]), 0.f);
                f2.y = fmaxf(fmaf(f2.y, di, bp[5]), 0.f);
                f3.x = fmaxf(fmaf(f3.x, di, bp[6]), 0.f);
                f3.y = fmaxf(fmaf(f3.y, di, bp[7]), 0.f);
                pk.h[0] = __floats2half2_rn(f0.x, f0.y);
                pk.h[1] = __floats2half2_rn(f1.x, f1.y);
                pk.h[2] = __floats2half2_rn(f2.x, f2.y);
                pk.h[3] = __floats2half2_rn(f3.x, f3.y);
            } else {
                float4 v0 = ((const float4*)xin)[grow * 32 + cn * 2];
                float4 v1 = ((const float4*)xin)[grow * 32 + cn * 2 + 1];
                pk.h[0] = __floats2half2_rn(v0.x, v0.y);
                pk.h[1] = __floats2half2_rn(v0.z, v0.w);
                pk.h[2] = __floats2half2_rn(v1.x, v1.y);
                pk.h[3] = __floats2half2_rn(v1.z, v1.w);
            }
            *(uint4*)(sA + row * 128 + ((cn ^ (row & 7)) << 3)) = pk.u;
        }
        __syncthreads();

        float c[2][4][4];
#pragma unroll
        for (int mt = 0; mt < 2; mt++)
#pragma unroll
            for (int nt = 0; nt < 4; nt++)
#pragma unroll
                for (int q = 0; q < 4; q++) c[mt][nt][q] = 0.f;

#pragma unroll
        for (int ks = 0; ks < 8; ks++) {
            uint32_t a[2][4];
#pragma unroll
            for (int mt = 0; mt < 2; mt++) {
                int r = wm * 32 + mt * 16 + (lane & 15);
                int ch = ks * 2 + (lane >> 4);
                uint32_t addr = sAu + (r << 8) + ((ch ^ (r & 7)) << 4);
                asm volatile("ldmatrix.sync.aligned.m8n8.x4.shared.b16 {%0,%1,%2,%3}, [%4];"
                             : "=r"(a[mt][0]), "=r"(a[mt][1]), "=r"(a[mt][2]), "=r"(a[mt][3])
                             : "r"(addr));
            }
            uint32_t b[4][2];
#pragma unroll
            for (int nt = 0; nt < 4; nt++) {
                int r = ks * 16 + (lane & 15);
                int ch = wn * 4 + nt;
                uint32_t addr = sBu + (r << 8) + ((ch ^ (r & 7)) << 4);
                asm volatile("ldmatrix.sync.aligned.m8n8.x2.trans.shared.b16 {%0,%1}, [%2];"
                             : "=r"(b[nt][0]), "=r"(b[nt][1])
                             : "r"(addr));
            }
#pragma unroll
            for (int mt = 0; mt < 2; mt++)
#pragma unroll
                for (int nt = 0; nt < 4; nt++) {
                    asm volatile(
                        "mma.sync.aligned.m16n8k16.row.col.f32.f16.f16.f32 "
                        "{%0,%1,%2,%3}, {%4,%5,%6,%7}, {%8,%9}, {%0,%1,%2,%3};"
                        : "+f"(c[mt][nt][0]), "+f"(c[mt][nt][1]),
                          "+f"(c[mt][nt][2]), "+f"(c[mt][nt][3])
                        : "r"(a[mt][0]), "r"(a[mt][1]), "r"(a[mt][2]), "r"(a[mt][3]),
                          "r"(b[nt][0]), "r"(b[nt][1]));
                }
        }

        // ---- Epilogue: * dinv[row], pack fp16, store.
#pragma unroll
        for (int mt = 0; mt < 2; mt++) {
            int Rb = r0 + wm * 32 + mt * 16 + (lane >> 2);
#pragma unroll
            for (int hf = 0; hf < 2; hf++) {
                int R = Rb + hf * 8;
                if (R < NODES) {
                    float di = g_dinv[R];
#pragma unroll
                    for (int nt = 0; nt < 4; nt++) {
                        int C = wn * 32 + nt * 8 + (lane & 3) * 2;
                        __half2 h = __floats2half2_rn(c[mt][nt][hf * 2 + 0] * di,
                                                      c[mt][nt][hf * 2 + 1] * di);
                        *(__half2*)(g_mh + R * 128 + C) = h;
                    }
                }
            }
        }
    }
}

// ---------------------------------------------------------------------------
// CSR aggregation: agg[n] = m[n] (self loop) + sum_{src in csr row n} m[src].
// One warp per node; 64-thread CTAs. Unroll 8. fp32 accumulate, fp16 store.
// ---------------------------------------------------------------------------
__global__ void __launch_bounds__(64) k_aggregate() {
    int node = blockIdx.x * 2 + (threadIdx.x >> 5);
    if (node >= NODES) return;
    int lane = threadIdx.x & 31;

    const __half* mh = g_mh;
    const int* __restrict__ csr = g_csr;

    float a0, a1, a2, a3;
    {   // self loop
        union { uint2 u; __half2 h[2]; } pk;
        pk.u = *(const uint2*)(mh + node * 128 + lane * 4);
        float2 f0 = __half22float2(pk.h[0]);
        float2 f1 = __half22float2(pk.h[1]);
        a0 = f0.x; a1 = f0.y; a2 = f1.x; a3 = f1.y;
    }

    int i = g_rowptr[node];
    int e = i + g_deg[node];

    for (; i + 8 <= e; i += 8) {
        int s[8];
#pragma unroll
        for (int j = 0; j < 8; j++) s[j] = __ldg(csr + i + j);
        union { uint2 u; __half2 h[2]; } p[8];
#pragma unroll
        for (int j = 0; j < 8; j++)
            p[j].u = *(const uint2*)(mh + s[j] * 128 + lane * 4);
#pragma unroll
        for (int j = 0; j < 8; j++) {
            float2 f;
            f = __half22float2(p[j].h[0]); a0 += f.x; a1 += f.y;
            f = __half22float2(p[j].h[1]); a2 += f.x; a3 += f.y;
        }
    }
    for (; i + 2 <= e; i += 2) {
        int s0 = __ldg(csr + i), s1 = __ldg(csr + i + 1);
        union { uint2 u; __half2 h[2]; } p0, p1;
        p0.u = *(const uint2*)(mh + s0 * 128 + lane * 4);
        p1.u = *(const uint2*)(mh + s1 * 128 + lane * 4);
        float2 f;
        f = __half22float2(p0.h[0]); a0 += f.x; a1 += f.y;
        f = __half22float2(p0.h[1]); a2 += f.x; a3 += f.y;
        f = __half22float2(p1.h[0]); a0 += f.x; a1 += f.y;
        f = __half22float2(p1.h[1]); a2 += f.x; a3 += f.y;
    }
    if (i < e) {
        int s0 = __ldg(csr + i);
        union { uint2 u; __half2 h[2]; } p0;
        p0.u = *(const uint2*)(mh + s0 * 128 + lane * 4);
        float2 f;
        f = __half22float2(p0.h[0]); a0 += f.x; a1 += f.y;
        f = __half22float2(p0.h[1]); a2 += f.x; a3 += f.y;
    }

    union { uint2 u; __half2 h[2]; } outp;
    outp.h[0] = __floats2half2_rn(a0, a1);
    outp.h[1] = __floats2half2_rn(a2, a3);
    *(uint2*)(g_aggh + node * 128 + lane * 4) = outp.u;
}

// ---------------------------------------------------------------------------
// Fused mean pool + head: block per graph, 128 threads.
// ---------------------------------------------------------------------------
__global__ void __launch_bounds__(128) k_pool_head(const int* __restrict__ batch,
                                                   const float* __restrict__ b3,
                                                   const float* __restrict__ Wl,
                                                   const float* __restrict__ bl,
                                                   float* __restrict__ out) {
    __shared__ float hg[DH];
    int g = blockIdx.x, t = threadIdx.x;
    int lo = 0, hi = NODES;
    while (lo < hi) { int m = (lo + hi) >> 1; if (batch[m] < g) lo = m + 1; else hi = m; }
    int s = lo;
    hi = NODES;
    while (lo < hi) { int m = (lo + hi) >> 1; if (batch[m] <= g) lo = m + 1; else hi = m; }
    int e = lo;

    float sum = 0.f;
    for (int n = s; n < e; n++)
        sum = fmaf(__half2float(g_aggh[n * 128 + t]), g_dinv[n], sum);
    int cnt = e - s;
    hg[t] = (cnt > 0) ? (sum / (float)cnt + b3[t]) : 0.f;
    __syncthreads();

    if (t < 32) {
        int lane = t;
        float acc[DOUT];
#pragma unroll
        for (int c = 0; c < DOUT; c++) acc[c] = 0.f;
        for (int k = lane; k < DH; k += 32) {
            float h = hg[k];
#pragma unroll
            for (int c = 0; c < DOUT; c++) acc[c] = fmaf(h, Wl[k * DOUT + c], acc[c]);
        }
#pragma unroll
        for (int off = 16; off > 0; off >>= 1)
#pragma unroll
            for (int c = 0; c < DOUT; c++)
                acc[c] += __shfl_xor_sync(0xFFFFFFFFu, acc[c], off);

        float mx = -1e30f;
#pragma unroll
        for (int c = 0; c < DOUT; c++) { acc[c] += bl[c]; mx = fmaxf(mx, acc[c]); }
        float ssum = 0.f;
#pragma unroll
        for (int c = 0; c < DOUT; c++) { acc[c] = expf(acc[c] - mx); ssum += acc[c]; }
        if (lane < DOUT) out[g * DOUT + lane] = acc[lane] / ssum;
    }
}

// ---------------------------------------------------------------------------
extern "C" void kernel_launch(void* const* d_in, const int* in_sizes, int n_in,
                              void* d_out, int out_size) {
    const float* x     = (const float*)d_in[0];
    const int*   ei    = (const int*)  d_in[1];
    const int*   batch = (const int*)  d_in[2];
    const float* W1 = (const float*)d_in[3];
    const float* b1 = (const float*)d_in[4];
    const float* W2 = (const float*)d_in[5];
    const float* b2 = (const float*)d_in[6];
    const float* W3 = (const float*)d_in[7];
    const float* b3 = (const float*)d_in[8];
    const float* Wl = (const float*)d_in[9];
    const float* bl = (const float*)d_in[10];
    float* out = (float*)d_out;

    const int agg_grid = (NODES + 1) / 2;

    // idx 0..2: degrees + fused CSR-alloc/weight-convert
    k_zero_deg    <<<(NODES + 255) / 256, 256>>>();
    k_count_deg   <<<(EDGES / 4 + 255) / 256, 256>>>(ei);
    k_alloc_wconv <<<NB + 24, 256>>>(W1, W2, W3);

    // idx 3: layer-1 GEMM (in the ncu capture slot)
    k_gemm_tc  <<<GEMM_GRID, 256>>>(x, 0, 0, nullptr);

    // idx 4: CSR fill (needed only by aggregation)
    k_csr_fill <<<(EDGES / 4 + 255) / 256, 256>>>(ei);

    // idx 5..9: aggregate / remaining layers
    k_aggregate<<<agg_grid, 64>>>();
    k_gemm_tc  <<<GEMM_GRID, 256>>>(nullptr, 1, 1, b1);
    k_aggregate<<<agg_grid, 64>>>();
    k_gemm_tc  <<<GEMM_GRID, 256>>>(nullptr, 1, 2, b2);
    k_aggregate<<<agg_grid, 64>>>();

    k_pool_head<<<GRAPHS, 128>>>(batch, b3, Wl, bl, out);
}

// round 11
// speedup vs baseline: 1.0347x; 1.0347x over previous
#include <cuda_runtime.h>
#include <cuda_fp16.h>
#include <cstdint>
#include <stdint.h>
#include <math.h>

// Problem constants (fixed by the reference)
constexpr int NODES  = 100000;
constexpr int EDGES  = 1600000;
constexpr int GRAPHS = 64;
constexpr int DH     = 128;   // DI == DH == 128
constexpr int DOUT   = 10;

constexpr int NB        = (NODES + 255) / 256;  // alloc blocks (391)
constexpr int GEMM_GRID = 521;                  // 1563 tiles = 3 * 521
constexpr int FILL_GRID = (EDGES / 4 + 255) / 256;  // 1563

// Scratch (device globals: allocation-free rule; zero-initialized at load).
// g_deg/g_total are re-zeroed by the TAIL kernel each call, so every call
// (first via load-time zero-init, later via tail) starts from zero.
__device__ __half  g_mh  [NODES * 128];   // messages m[i] = (h@W)*dinv[i], fp16
__device__ __half  g_aggh[NODES * 128];   // aggregate, fp16 (fp32 accum in regs)
__device__ __half  g_wh  [3 * 128 * 128]; // all 3 layers' weights, fp16, swizzled
__device__ int     g_deg [NODES];
__device__ float   g_dinv[NODES];
__device__ int     g_rowptr[NODES];       // CSR row start (end = start + deg)
__device__ int     g_cursor[NODES];
__device__ int     g_csr[EDGES];          // src indices grouped by dst
__device__ int     g_total;               // global CSR allocation cursor

// ---------------------------------------------------------------------------
// Degree count (g_deg is zero on entry; see note above).
// ---------------------------------------------------------------------------
__global__ void k_count_deg(const int* __restrict__ ei) {   // 4 edges/thread
    int e4 = blockIdx.x * blockDim.x + threadIdx.x;
    if (e4 < EDGES / 4) {
        int4 d = ((const int4*)(ei + EDGES))[e4];
        atomicAdd(&g_deg[d.x], 1);
        atomicAdd(&g_deg[d.y], 1);
        atomicAdd(&g_deg[d.z], 1);
        atomicAdd(&g_deg[d.w], 1);
    }
}

// ---------------------------------------------------------------------------
// Fused CSR allocation + weight convert. Blocks [0,NB): block-local scan +
// one atomicAdd for the block's base (allocation order across blocks is
// arbitrary but always a valid disjoint layout) + dinv.
// Blocks [NB, NB+24): convert the 3 weight matrices fp32 -> fp16 swizzled.
// ---------------------------------------------------------------------------
__global__ void k_alloc_wconv(const float* __restrict__ W1,
                              const float* __restrict__ W2,
                              const float* __restrict__ W3) {
    if (blockIdx.x >= NB) {
        int gchunk = (blockIdx.x - NB) * 256 + threadIdx.x;   // 0..6143
        int layer = gchunk >> 11;                              // 0..2
        int chunk = gchunk & 2047;
        int row = chunk >> 4, cn = chunk & 15;
        const float* W = (layer == 0) ? W1 : (layer == 1) ? W2 : W3;
        const float4* W4 = (const float4*)W;
        float4 v0 = W4[row * 32 + cn * 2];
        float4 v1 = W4[row * 32 + cn * 2 + 1];
        union { uint4 u; __half2 h[4]; } pk;
        pk.h[0] = __floats2half2_rn(v0.x, v0.y);
        pk.h[1] = __floats2half2_rn(v0.z, v0.w);
        pk.h[2] = __floats2half2_rn(v1.x, v1.y);
        pk.h[3] = __floats2half2_rn(v1.z, v1.w);
        *(uint4*)(g_wh + layer * 128 * 128 + row * 128 + ((cn ^ (row & 7)) << 3)) = pk.u;
        return;
    }
    __shared__ int sh[256];
    __shared__ int sbase;
    int i = blockIdx.x * 256 + threadIdx.x;
    int t = threadIdx.x;
    int v = (i < NODES) ? g_deg[i] : 0;
    sh[t] = v;
    __syncthreads();
    for (int off = 1; off < 256; off <<= 1) {
        int add = (t >= off) ? sh[t - off] : 0;
        __syncthreads();
        sh[t] += add;
        __syncthreads();
    }
    if (t == 255) sbase = atomicAdd(&g_total, sh[255]);
    __syncthreads();
    if (i < NODES) {
        int start = sbase + sh[t] - v;       // exclusive within block + base
        g_rowptr[i] = start;
        g_cursor[i] = start;
        g_dinv[i] = rsqrtf((float)(v + 1));  // +1 self loop
    }
}

// ---------------------------------------------------------------------------
// GEMM body (device function): m_row = (pre(in_row)) @ W * dinv[row] -> g_mh.
// pre(in) = in                      (use_pre == 0, first layer reads fp32 x)
// pre(in) = relu(in*dinv[row] + b)  (use_pre == 1, reads fp16 g_aggh)
// Loads sB once, processes 3 x 64-row tiles (1563 = 3*521, balanced wave).
// 8 warps, 2(m) x 4(n). XOR-swizzled smem, ldmatrix + mma.m16n8k16.
// ---------------------------------------------------------------------------
__device__ __forceinline__ uint32_t s2u(const void* p) {
    return (uint32_t)__cvta_generic_to_shared(p);
}

__device__ __forceinline__ void gemm_body(__half* sA, __half* sB, int blockid,
                                          const float* __restrict__ xin,
                                          int use_pre, int wlayer,
                                          const float* __restrict__ bias) {
    const int tid = threadIdx.x;

    // ---- B: raw copy of pre-swizzled fp16 weights (2048 x 16B), once.
    const uint4* wsrc = (const uint4*)(g_wh + wlayer * 128 * 128);
    uint4* bdst = (uint4*)sB;
#pragma unroll
    for (int i = 0; i < 8; i++) bdst[i * 256 + tid] = __ldg(wsrc + i * 256 + tid);

    const int lane = tid & 31, wid = tid >> 5;
    const int wm = wid & 1;        // 2 warps over m (32 rows each)
    const int wn = wid >> 1;       // 4 warps over n (32 cols each)
    const uint32_t sAu = s2u(sA), sBu = s2u(sB);

#pragma unroll 1
    for (int it = 0; it < 3; it++) {
        const int r0 = (blockid + it * GEMM_GRID) * 64;
        if (it) __syncthreads();       // all reads of previous sA done

        // ---- A tile [64][128] with fused pre-transform. 1024 chunks of 16B.
#pragma unroll
        for (int i = 0; i < 4; i++) {
            int chunk = i * 256 + tid;
            int row = chunk >> 4, cn = chunk & 15;
            int grow = r0 + row;
            union { uint4 u; __half2 h[4]; } pk;
            if (grow >= NODES) {
                pk.u = make_uint4(0, 0, 0, 0);
            } else if (use_pre) {
                union { uint4 u; __half2 h[4]; } in;
                in.u = *(const uint4*)(g_aggh + grow * 128 + cn * 8);
                float di = g_dinv[grow];
                const float* bp = bias + cn * 8;
                float2 f0 = __half22float2(in.h[0]);
                float2 f1 = __half22float2(in.h[1]);
                float2 f2 = __half22float2(in.h[2]);
                float2 f3 = __half22float2(in.h[3]);
                f0.x = fmaxf(fmaf(f0.x, di, bp[0]), 0.f);
                f0.y = fmaxf(fmaf(f0.y, di, bp[1]), 0.f);
                f1.x = fmaxf(fmaf(f1.x, di, bp[2]), 0.f);
                f1.y = fmaxf(fmaf(f1.y, di, bp[3]), 0.f);
                f2.x = fmaxf(fmaf(f2.x, di, bp[4]), 0.f);
                f2.y = fmaxf(fmaf(f2.y, di, bp[5]), 0.f);
                f3.x = fmaxf(fmaf(f3.x, di, bp[6]), 0.f);
                f3.y = fmaxf(fmaf(f3.y, di, bp[7]), 0.f);
                pk.h[0] = __floats2half2_rn(f0.x, f0.y);
                pk.h[1] = __floats2half2_rn(f1.x, f1.y);
                pk.h[2] = __floats2half2_rn(f2.x, f2.y);
                pk.h[3] = __floats2half2_rn(f3.x, f3.y);
            } else {
                float4 v0 = ((const float4*)xin)[grow * 32 + cn * 2];
                float4 v1 = ((const float4*)xin)[grow * 32 + cn * 2 + 1];
                pk.h[0] = __floats2half2_rn(v0.x, v0.y);
                pk.h[1] = __floats2half2_rn(v0.z, v0.w);
                pk.h[2] = __floats2half2_rn(v1.x, v1.y);
                pk.h[3] = __floats2half2_rn(v1.z, v1.w);
            }
            *(uint4*)(sA + row * 128 + ((cn ^ (row & 7)) << 3)) = pk.u;
        }
        __syncthreads();

        float c[2][4][4];
#pragma unroll
        for (int mt = 0; mt < 2; mt++)
#pragma unroll
            for (int nt = 0; nt < 4; nt++)
#pragma unroll
                for (int q = 0; q < 4; q++) c[mt][nt][q] = 0.f;

#pragma unroll
        for (int ks = 0; ks < 8; ks++) {
            uint32_t a[2][4];
#pragma unroll
            for (int mt = 0; mt < 2; mt++) {
                int r = wm * 32 + mt * 16 + (lane & 15);
                int ch = ks * 2 + (lane >> 4);
                uint32_t addr = sAu + (r << 8) + ((ch ^ (r & 7)) << 4);
                asm volatile("ldmatrix.sync.aligned.m8n8.x4.shared.b16 {%0,%1,%2,%3}, [%4];"
                             : "=r"(a[mt][0]), "=r"(a[mt][1]), "=r"(a[mt][2]), "=r"(a[mt][3])
                             : "r"(addr));
            }
            uint32_t b[4][2];
#pragma unroll
            for (int nt = 0; nt < 4; nt++) {
                int r = ks * 16 + (lane & 15);
                int ch = wn * 4 + nt;
                uint32_t addr = sBu + (r << 8) + ((ch ^ (r & 7)) << 4);
                asm volatile("ldmatrix.sync.aligned.m8n8.x2.trans.shared.b16 {%0,%1}, [%2];"
                             : "=r"(b[nt][0]), "=r"(b[nt][1])
                             : "r"(addr));
            }
#pragma unroll
            for (int mt = 0; mt < 2; mt++)
#pragma unroll
                for (int nt = 0; nt < 4; nt++) {
                    asm volatile(
                        "mma.sync.aligned.m16n8k16.row.col.f32.f16.f16.f32 "
                        "{%0,%1,%2,%3}, {%4,%5,%6,%7}, {%8,%9}, {%0,%1,%2,%3};"
                        : "+f"(c[mt][nt][0]), "+f"(c[mt][nt][1]),
                          "+f"(c[mt][nt][2]), "+f"(c[mt][nt][3])
                        : "r"(a[mt][0]), "r"(a[mt][1]), "r"(a[mt][2]), "r"(a[mt][3]),
                          "r"(b[nt][0]), "r"(b[nt][1]));
                }
        }

        // ---- Epilogue: * dinv[row], pack fp16, store.
#pragma unroll
        for (int mt = 0; mt < 2; mt++) {
            int Rb = r0 + wm * 32 + mt * 16 + (lane >> 2);
#pragma unroll
            for (int hf = 0; hf < 2; hf++) {
                int R = Rb + hf * 8;
                if (R < NODES) {
                    float di = g_dinv[R];
#pragma unroll
                    for (int nt = 0; nt < 4; nt++) {
                        int C = wn * 32 + nt * 8 + (lane & 3) * 2;
                        __half2 h = __floats2half2_rn(c[mt][nt][hf * 2 + 0] * di,
                                                      c[mt][nt][hf * 2 + 1] * di);
                        *(__half2*)(g_mh + R * 128 + C) = h;
                    }
                }
            }
        }
    }
}

__device__ __forceinline__ void fill_body(const int* __restrict__ ei, int blockid) {
    int e4 = blockid * 256 + threadIdx.x;
    if (e4 < EDGES / 4) {
        int4 s = ((const int4*)ei)[e4];
        int4 d = ((const int4*)(ei + EDGES))[e4];
        g_csr[atomicAdd(&g_cursor[d.x], 1)] = s.x;
        g_csr[atomicAdd(&g_cursor[d.y], 1)] = s.y;
        g_csr[atomicAdd(&g_cursor[d.z], 1)] = s.z;
        g_csr[atomicAdd(&g_cursor[d.w], 1)] = s.w;
    }
}

// Layer-1 GEMM fused with CSR fill (independent workloads, disjoint blocks;
// they overlap: gemm is DRAM-stream-bound, fill is atomic-latency-bound).
__global__ void __launch_bounds__(256) k_gemm1_fill(const float* __restrict__ xin,
                                                    const int* __restrict__ ei) {
    __shared__ __align__(16) __half sA[64 * 128];
    __shared__ __align__(16) __half sB[128 * 128];
    if (blockIdx.x < GEMM_GRID) {
        gemm_body(sA, sB, blockIdx.x, xin, 0, 0, nullptr);
    } else {
        fill_body(ei, blockIdx.x - GEMM_GRID);
    }
}

// Layers 2/3 GEMM.
__global__ void __launch_bounds__(256) k_gemm_tc(int wlayer,
                                                 const float* __restrict__ bias) {
    __shared__ __align__(16) __half sA[64 * 128];
    __shared__ __align__(16) __half sB[128 * 128];
    gemm_body(sA, sB, blockIdx.x, nullptr, 1, wlayer, bias);
}

// ---------------------------------------------------------------------------
// CSR aggregation: agg[n] = m[n] (self loop) + sum_{src in csr row n} m[src].
// One warp per node; 64-thread CTAs. Unroll 8. fp32 accumulate, fp16 store.
// (Unchanged from round 9/10 so the ncu capture measures the current impl.)
// ---------------------------------------------------------------------------
__global__ void __launch_bounds__(64) k_aggregate() {
    int node = blockIdx.x * 2 + (threadIdx.x >> 5);
    if (node >= NODES) return;
    int lane = threadIdx.x & 31;

    const __half* mh = g_mh;
    const int* __restrict__ csr = g_csr;

    float a0, a1, a2, a3;
    {   // self loop
        union { uint2 u; __half2 h[2]; } pk;
        pk.u = *(const uint2*)(mh + node * 128 + lane * 4);
        float2 f0 = __half22float2(pk.h[0]);
        float2 f1 = __half22float2(pk.h[1]);
        a0 = f0.x; a1 = f0.y; a2 = f1.x; a3 = f1.y;
    }

    int i = g_rowptr[node];
    int e = i + g_deg[node];

    for (; i + 8 <= e; i += 8) {
        int s[8];
#pragma unroll
        for (int j = 0; j < 8; j++) s[j] = __ldg(csr + i + j);
        union { uint2 u; __half2 h[2]; } p[8];
#pragma unroll
        for (int j = 0; j < 8; j++)
            p[j].u = *(const uint2*)(mh + s[j] * 128 + lane * 4);
#pragma unroll
        for (int j = 0; j < 8; j++) {
            float2 f;
            f = __half22float2(p[j].h[0]); a0 += f.x; a1 += f.y;
            f = __half22float2(p[j].h[1]); a2 += f.x; a3 += f.y;
        }
    }
    for (; i + 2 <= e; i += 2) {
        int s0 = __ldg(csr + i), s1 = __ldg(csr + i + 1);
        union { uint2 u; __half2 h[2]; } p0, p1;
        p0.u = *(const uint2*)(mh + s0 * 128 + lane * 4);
        p1.u = *(const uint2*)(mh + s1 * 128 + lane * 4);
        float2 f;
        f = __half22float2(p0.h[0]); a0 += f.x; a1 += f.y;
        f = __half22float2(p0.h[1]); a2 += f.x; a3 += f.y;
        f = __half22float2(p1.h[0]); a0 += f.x; a1 += f.y;
        f = __half22float2(p1.h[1]); a2 += f.x; a3 += f.y;
    }
    if (i < e) {
        int s0 = __ldg(csr + i);
        union { uint2 u; __half2 h[2]; } p0;
        p0.u = *(const uint2*)(mh + s0 * 128 + lane * 4);
        float2 f;
        f = __half22float2(p0.h[0]); a0 += f.x; a1 += f.y;
        f = __half22float2(p0.h[1]); a2 += f.x; a3 += f.y;
    }

    union { uint2 u; __half2 h[2]; } outp;
    outp.h[0] = __floats2half2_rn(a0, a1);
    outp.h[1] = __floats2half2_rn(a2, a3);
    *(uint2*)(g_aggh + node * 128 + lane * 4) = outp.u;
}

// ---------------------------------------------------------------------------
// Tail: fused mean pool + head (blocks [0,64)) AND re-zero g_deg/g_total for
// the next call (blocks [64, 64+782)). Load-time zero-init covers call 1.
// ---------------------------------------------------------------------------
__global__ void __launch_bounds__(128) k_pool_head_zero(
        const int* __restrict__ batch, const float* __restrict__ b3,
        const float* __restrict__ Wl, const float* __restrict__ bl,
        float* __restrict__ out) {
    if (blockIdx.x >= GRAPHS) {
        int i = (blockIdx.x - GRAPHS) * 128 + threadIdx.x;
        if (i < NODES) g_deg[i] = 0;
        if (i == 0) g_total = 0;
        return;
    }
    __shared__ float hg[DH];
    int g = blockIdx.x, t = threadIdx.x;
    int lo = 0, hi = NODES;
    while (lo < hi) { int m = (lo + hi) >> 1; if (batch[m] < g) lo = m + 1; else hi = m; }
    int s = lo;
    hi = NODES;
    while (lo < hi) { int m = (lo + hi) >> 1; if (batch[m] <= g) lo = m + 1; else hi = m; }
    int e = lo;

    float sum = 0.f;
    for (int n = s; n < e; n++)
        sum = fmaf(__half2float(g_aggh[n * 128 + t]), g_dinv[n], sum);
    int cnt = e - s;
    hg[t] = (cnt > 0) ? (sum / (float)cnt + b3[t]) : 0.f;
    __syncthreads();

    if (t < 32) {
        int lane = t;
        float acc[DOUT];
#pragma unroll
        for (int c = 0; c < DOUT; c++) acc[c] = 0.f;
        for (int k = lane; k < DH; k += 32) {
            float h = hg[k];
#pragma unroll
            for (int c = 0; c < DOUT; c++) acc[c] = fmaf(h, Wl[k * DOUT + c], acc[c]);
        }
#pragma unroll
        for (int off = 16; off > 0; off >>= 1)
#pragma unroll
            for (int c = 0; c < DOUT; c++)
                acc[c] += __shfl_xor_sync(0xFFFFFFFFu, acc[c], off);

        float mx = -1e30f;
#pragma unroll
        for (int c = 0; c < DOUT; c++) { acc[c] += bl[c]; mx = fmaxf(mx, acc[c]); }
        float ssum = 0.f;
#pragma unroll
        for (int c = 0; c < DOUT; c++) { acc[c] = expf(acc[c] - mx); ssum += acc[c]; }
        if (lane < DOUT) out[g * DOUT + lane] = acc[lane] / ssum;
    }
}

// ---------------------------------------------------------------------------
extern "C" void kernel_launch(void* const* d_in, const int* in_sizes, int n_in,
                              void* d_out, int out_size) {
    const float* x     = (const float*)d_in[0];
    const int*   ei    = (const int*)  d_in[1];
    const int*   batch = (const int*)  d_in[2];
    const float* W1 = (const float*)d_in[3];
    const float* b1 = (const float*)d_in[4];
    const float* W2 = (const float*)d_in[5];
    const float* b2 = (const float*)d_in[6];
    const float* W3 = (const float*)d_in[7];
    const float* b3 = (const float*)d_in[8];
    const float* Wl = (const float*)d_in[9];
    const float* bl = (const float*)d_in[10];
    float* out = (float*)d_out;

    const int agg_grid  = (NODES + 1) / 2;
    const int zero_blocks = (NODES + 127) / 128;   // 782

    // idx 0: degree count (g_deg zeroed by tail of previous call / load-init)
    k_count_deg   <<<(EDGES / 4 + 255) / 256, 256>>>(ei);
    // idx 1: CSR alloc + dinv + weight convert
    k_alloc_wconv <<<NB + 24, 256>>>(W1, W2, W3);
    // idx 2: layer-1 GEMM overlapped with CSR fill
    k_gemm1_fill  <<<GEMM_GRID + FILL_GRID, 256>>>(x, ei);
    // idx 3: aggregate layer 1  (ncu capture slot)
    k_aggregate   <<<agg_grid, 64>>>();
    // idx 4..7: layers 2, 3
    k_gemm_tc     <<<GEMM_GRID, 256>>>(1, b1);
    k_aggregate   <<<agg_grid, 64>>>();
    k_gemm_tc     <<<GEMM_GRID, 256>>>(2, b2);
    k_aggregate   <<<agg_grid, 64>>>();
    // idx 8: pool + head + re-zero degree state for next call
    k_pool_head_zero<<<GRAPHS + zero_blocks, 128>>>(batch, b3, Wl, bl, out);
}

// round 12
// speedup vs baseline: 1.0793x; 1.0431x over previous
#include <cuda_runtime.h>
#include <cuda_fp16.h>
#include <cstdint>
#include <stdint.h>
#include <math.h>

// Problem constants (fixed by the reference)
constexpr int NODES  = 100000;
constexpr int EDGES  = 1600000;
constexpr int GRAPHS = 64;
constexpr int DH     = 128;   // DI == DH == 128
constexpr int DOUT   = 10;

constexpr int NB        = (NODES + 255) / 256;  // alloc blocks (391)
constexpr int GEMM_GRID = 521;                  // 1563 tiles = 3 * 521
constexpr int FILL_GRID = (EDGES / 4 + 255) / 256;  // 1563

// Scratch (device globals: allocation-free rule; zero-initialized at load).
// g_deg/g_total are re-zeroed by the TAIL kernel each call, so every call
// (first via load-time zero-init, later via tail) starts from zero.
__device__ __half  g_mh  [NODES * 128];   // messages m[i] = (h@W)*dinv[i], fp16
__device__ __half  g_aggh[NODES * 128];   // aggregate, fp16 (fp32 accum in regs)
__device__ __half  g_wh  [3 * 128 * 128]; // all 3 layers' weights, fp16, swizzled
__device__ int     g_deg [NODES];
__device__ float   g_dinv[NODES];
__device__ int     g_rowptr[NODES];       // CSR row start (end = start + deg)
__device__ int     g_cursor[NODES];
__device__ int     g_csr[EDGES];          // src indices grouped by dst
__device__ int     g_total;               // global CSR allocation cursor

// ---------------------------------------------------------------------------
// Degree count (g_deg is zero on entry; see note above).
// ---------------------------------------------------------------------------
__global__ void k_count_deg(const int* __restrict__ ei) {   // 4 edges/thread
    int e4 = blockIdx.x * blockDim.x + threadIdx.x;
    if (e4 < EDGES / 4) {
        int4 d = ((const int4*)(ei + EDGES))[e4];
        atomicAdd(&g_deg[d.x], 1);
        atomicAdd(&g_deg[d.y], 1);
        atomicAdd(&g_deg[d.z], 1);
        atomicAdd(&g_deg[d.w], 1);
    }
}

// ---------------------------------------------------------------------------
// Fused CSR allocation + weight convert. Blocks [0,NB): block-local scan +
// one atomicAdd for the block's base (allocation order across blocks is
// arbitrary but always a valid disjoint layout) + dinv.
// Blocks [NB, NB+24): convert the 3 weight matrices fp32 -> fp16 swizzled.
// ---------------------------------------------------------------------------
__global__ void k_alloc_wconv(const float* __restrict__ W1,
                              const float* __restrict__ W2,
                              const float* __restrict__ W3) {
    if (blockIdx.x >= NB) {
        int gchunk = (blockIdx.x - NB) * 256 + threadIdx.x;   // 0..6143
        int layer = gchunk >> 11;                              // 0..2
        int chunk = gchunk & 2047;
        int row = chunk >> 4, cn = chunk & 15;
        const float* W = (layer == 0) ? W1 : (layer == 1) ? W2 : W3;
        const float4* W4 = (const float4*)W;
        float4 v0 = W4[row * 32 + cn * 2];
        float4 v1 = W4[row * 32 + cn * 2 + 1];
        union { uint4 u; __half2 h[4]; } pk;
        pk.h[0] = __floats2half2_rn(v0.x, v0.y);
        pk.h[1] = __floats2half2_rn(v0.z, v0.w);
        pk.h[2] = __floats2half2_rn(v1.x, v1.y);
        pk.h[3] = __floats2half2_rn(v1.z, v1.w);
        *(uint4*)(g_wh + layer * 128 * 128 + row * 128 + ((cn ^ (row & 7)) << 3)) = pk.u;
        return;
    }
    __shared__ int sh[256];
    __shared__ int sbase;
    int i = blockIdx.x * 256 + threadIdx.x;
    int t = threadIdx.x;
    int v = (i < NODES) ? g_deg[i] : 0;
    sh[t] = v;
    __syncthreads();
    for (int off = 1; off < 256; off <<= 1) {
        int add = (t >= off) ? sh[t - off] : 0;
        __syncthreads();
        sh[t] += add;
        __syncthreads();
    }
    if (t == 255) sbase = atomicAdd(&g_total, sh[255]);
    __syncthreads();
    if (i < NODES) {
        int start = sbase + sh[t] - v;       // exclusive within block + base
        g_rowptr[i] = start;
        g_cursor[i] = start;
        g_dinv[i] = rsqrtf((float)(v + 1));  // +1 self loop
    }
}

// ---------------------------------------------------------------------------
// GEMM body (device function): m_row = (pre(in_row)) @ W * dinv[row] -> g_mh.
// pre(in) = in                      (use_pre == 0, first layer reads fp32 x)
// pre(in) = relu(in*dinv[row] + b)  (use_pre == 1, reads fp16 g_aggh)
// Loads sB once, processes 3 x 64-row tiles (1563 = 3*521, balanced wave).
// 8 warps, 2(m) x 4(n). XOR-swizzled smem, ldmatrix + mma.m16n8k16.
// ---------------------------------------------------------------------------
__device__ __forceinline__ uint32_t s2u(const void* p) {
    return (uint32_t)__cvta_generic_to_shared(p);
}

__device__ __forceinline__ void gemm_body(__half* sA, __half* sB, int blockid,
                                          const float* __restrict__ xin,
                                          int use_pre, int wlayer,
                                          const float* __restrict__ bias) {
    const int tid = threadIdx.x;

    // ---- B: raw copy of pre-swizzled fp16 weights (2048 x 16B), once.
    const uint4* wsrc = (const uint4*)(g_wh + wlayer * 128 * 128);
    uint4* bdst = (uint4*)sB;
#pragma unroll
    for (int i = 0; i < 8; i++) bdst[i * 256 + tid] = __ldg(wsrc + i * 256 + tid);

    const int lane = tid & 31, wid = tid >> 5;
    const int wm = wid & 1;        // 2 warps over m (32 rows each)
    const int wn = wid >> 1;       // 4 warps over n (32 cols each)
    const uint32_t sAu = s2u(sA), sBu = s2u(sB);

#pragma unroll 1
    for (int it = 0; it < 3; it++) {
        const int r0 = (blockid + it * GEMM_GRID) * 64;
        if (it) __syncthreads();       // all reads of previous sA done

        // ---- A tile [64][128] with fused pre-transform. 1024 chunks of 16B.
#pragma unroll
        for (int i = 0; i < 4; i++) {
            int chunk = i * 256 + tid;
            int row = chunk >> 4, cn = chunk & 15;
            int grow = r0 + row;
            union { uint4 u; __half2 h[4]; } pk;
            if (grow >= NODES) {
                pk.u = make_uint4(0, 0, 0, 0);
            } else if (use_pre) {
                union { uint4 u; __half2 h[4]; } in;
                in.u = *(const uint4*)(g_aggh + grow * 128 + cn * 8);
                float di = g_dinv[grow];
                const float* bp = bias + cn * 8;
                float2 f0 = __half22float2(in.h[0]);
                float2 f1 = __half22float2(in.h[1]);
                float2 f2 = __half22float2(in.h[2]);
                float2 f3 = __half22float2(in.h[3]);
                f0.x = fmaxf(fmaf(f0.x, di, bp[0]), 0.f);
                f0.y = fmaxf(fmaf(f0.y, di, bp[1]), 0.f);
                f1.x = fmaxf(fmaf(f1.x, di, bp[2]), 0.f);
                f1.y = fmaxf(fmaf(f1.y, di, bp[3]), 0.f);
                f2.x = fmaxf(fmaf(f2.x, di, bp[4]), 0.f);
                f2.y = fmaxf(fmaf(f2.y, di, bp[5]), 0.f);
                f3.x = fmaxf(fmaf(f3.x, di, bp[6]), 0.f);
                f3.y = fmaxf(fmaf(f3.y, di, bp[7]), 0.f);
                pk.h[0] = __floats2half2_rn(f0.x, f0.y);
                pk.h[1] = __floats2half2_rn(f1.x, f1.y);
                pk.h[2] = __floats2half2_rn(f2.x, f2.y);
                pk.h[3] = __floats2half2_rn(f3.x, f3.y);
            } else {
                float4 v0 = ((const float4*)xin)[grow * 32 + cn * 2];
                float4 v1 = ((const float4*)xin)[grow * 32 + cn * 2 + 1];
                pk.h[0] = __floats2half2_rn(v0.x, v0.y);
                pk.h[1] = __floats2half2_rn(v0.z, v0.w);
                pk.h[2] = __floats2half2_rn(v1.x, v1.y);
                pk.h[3] = __floats2half2_rn(v1.z, v1.w);
            }
            *(uint4*)(sA + row * 128 + ((cn ^ (row & 7)) << 3)) = pk.u;
        }
        __syncthreads();

        float c[2][4][4];
#pragma unroll
        for (int mt = 0; mt < 2; mt++)
#pragma unroll
            for (int nt = 0; nt < 4; nt++)
#pragma unroll
                for (int q = 0; q < 4; q++) c[mt][nt][q] = 0.f;

#pragma unroll
        for (int ks = 0; ks < 8; ks++) {
            uint32_t a[2][4];
#pragma unroll
            for (int mt = 0; mt < 2; mt++) {
                int r = wm * 32 + mt * 16 + (lane & 15);
                int ch = ks * 2 + (lane >> 4);
                uint32_t addr = sAu + (r << 8) + ((ch ^ (r & 7)) << 4);
                asm volatile("ldmatrix.sync.aligned.m8n8.x4.shared.b16 {%0,%1,%2,%3}, [%4];"
                             : "=r"(a[mt][0]), "=r"(a[mt][1]), "=r"(a[mt][2]), "=r"(a[mt][3])
                             : "r"(addr));
            }
            uint32_t b[4][2];
#pragma unroll
            for (int nt = 0; nt < 4; nt++) {
                int r = ks * 16 + (lane & 15);
                int ch = wn * 4 + nt;
                uint32_t addr = sBu + (r << 8) + ((ch ^ (r & 7)) << 4);
                asm volatile("ldmatrix.sync.aligned.m8n8.x2.trans.shared.b16 {%0,%1}, [%2];"
                             : "=r"(b[nt][0]), "=r"(b[nt][1])
                             : "r"(addr));
            }
#pragma unroll
            for (int mt = 0; mt < 2; mt++)
#pragma unroll
                for (int nt = 0; nt < 4; nt++) {
                    asm volatile(
                        "mma.sync.aligned.m16n8k16.row.col.f32.f16.f16.f32 "
                        "{%0,%1,%2,%3}, {%4,%5,%6,%7}, {%8,%9}, {%0,%1,%2,%3};"
                        : "+f"(c[mt][nt][0]), "+f"(c[mt][nt][1]),
                          "+f"(c[mt][nt][2]), "+f"(c[mt][nt][3])
                        : "r"(a[mt][0]), "r"(a[mt][1]), "r"(a[mt][2]), "r"(a[mt][3]),
                          "r"(b[nt][0]), "r"(b[nt][1]));
                }
        }

        // ---- Epilogue: * dinv[row], pack fp16, store.
#pragma unroll
        for (int mt = 0; mt < 2; mt++) {
            int Rb = r0 + wm * 32 + mt * 16 + (lane >> 2);
#pragma unroll
            for (int hf = 0; hf < 2; hf++) {
                int R = Rb + hf * 8;
                if (R < NODES) {
                    float di = g_dinv[R];
#pragma unroll
                    for (int nt = 0; nt < 4; nt++) {
                        int C = wn * 32 + nt * 8 + (lane & 3) * 2;
                        __half2 h = __floats2half2_rn(c[mt][nt][hf * 2 + 0] * di,
                                                      c[mt][nt][hf * 2 + 1] * di);
                        *(__half2*)(g_mh + R * 128 + C) = h;
                    }
                }
            }
        }
    }
}

__device__ __forceinline__ void fill_body(const int* __restrict__ ei, int blockid) {
    int e4 = blockid * 256 + threadIdx.x;
    if (e4 < EDGES / 4) {
        int4 s = ((const int4*)ei)[e4];
        int4 d = ((const int4*)(ei + EDGES))[e4];
        g_csr[atomicAdd(&g_cursor[d.x], 1)] = s.x;
        g_csr[atomicAdd(&g_cursor[d.y], 1)] = s.y;
        g_csr[atomicAdd(&g_cursor[d.z], 1)] = s.z;
        g_csr[atomicAdd(&g_cursor[d.w], 1)] = s.w;
    }
}

// Layer-1 GEMM fused with CSR fill (independent workloads, disjoint blocks).
__global__ void __launch_bounds__(256) k_gemm1_fill(const float* __restrict__ xin,
                                                    const int* __restrict__ ei) {
    __shared__ __align__(16) __half sA[64 * 128];
    __shared__ __align__(16) __half sB[128 * 128];
    if (blockIdx.x < GEMM_GRID) {
        gemm_body(sA, sB, blockIdx.x, xin, 0, 0, nullptr);
    } else {
        fill_body(ei, blockIdx.x - GEMM_GRID);
    }
}

// Layers 2/3 GEMM.
__global__ void __launch_bounds__(256) k_gemm_tc(int wlayer,
                                                 const float* __restrict__ bias) {
    __shared__ __align__(16) __half sA[64 * 128];
    __shared__ __align__(16) __half sB[128 * 128];
    gemm_body(sA, sB, blockIdx.x, nullptr, 1, wlayer, bias);
}

// ---------------------------------------------------------------------------
// CSR aggregation: agg[n] = m[n] (self loop) + sum_{src in csr row n} m[src].
// One warp per node; 64-thread CTAs. ISSUE-BOUND (ncu R11: issue 79.6%,
// alu 51%) -> cut instructions: 8-neighbor batches summed with a depth-3
// HALF2 adder tree (14 HADD2 + 4 cvt + 4 FADD per batch, vs 64 cvt/FADD).
// Cross-batch master accumulator stays fp32.
// ---------------------------------------------------------------------------
__global__ void __launch_bounds__(64) k_aggregate() {
    int node = blockIdx.x * 2 + (threadIdx.x >> 5);
    if (node >= NODES) return;
    int lane = threadIdx.x & 31;

    const __half* mh = g_mh;
    const int* __restrict__ csr = g_csr;

    float a0, a1, a2, a3;
    {   // self loop (fp32 path)
        union { uint2 u; __half2 h[2]; } pk;
        pk.u = *(const uint2*)(mh + node * 128 + lane * 4);
        float2 f0 = __half22float2(pk.h[0]);
        float2 f1 = __half22float2(pk.h[1]);
        a0 = f0.x; a1 = f0.y; a2 = f1.x; a3 = f1.y;
    }

    int i = g_rowptr[node];
    int e = i + g_deg[node];

    for (; i + 8 <= e; i += 8) {
        int s[8];
#pragma unroll
        for (int j = 0; j < 8; j++) s[j] = __ldg(csr + i + j);
        union { uint2 u; __half2 h[2]; } p[8];
#pragma unroll
        for (int j = 0; j < 8; j++)
            p[j].u = *(const uint2*)(mh + s[j] * 128 + lane * 4);
        // depth-3 half2 adder tree over the 8 neighbors (per half2 register)
        __half2 t0, t1;
        {
            __half2 q01 = __hadd2(p[0].h[0], p[1].h[0]);
            __half2 q23 = __hadd2(p[2].h[0], p[3].h[0]);
            __half2 q45 = __hadd2(p[4].h[0], p[5].h[0]);
            __half2 q67 = __hadd2(p[6].h[0], p[7].h[0]);
            t0 = __hadd2(__hadd2(q01, q23), __hadd2(q45, q67));
        }
        {
            __half2 q01 = __hadd2(p[0].h[1], p[1].h[1]);
            __half2 q23 = __hadd2(p[2].h[1], p[3].h[1]);
            __half2 q45 = __hadd2(p[4].h[1], p[5].h[1]);
            __half2 q67 = __hadd2(p[6].h[1], p[7].h[1]);
            t1 = __hadd2(__hadd2(q01, q23), __hadd2(q45, q67));
        }
        float2 f0 = __half22float2(t0);
        float2 f1 = __half22float2(t1);
        a0 += f0.x; a1 += f0.y; a2 += f1.x; a3 += f1.y;
    }
    for (; i + 2 <= e; i += 2) {
        int s0 = __ldg(csr + i), s1 = __ldg(csr + i + 1);
        union { uint2 u; __half2 h[2]; } p0, p1;
        p0.u = *(const uint2*)(mh + s0 * 128 + lane * 4);
        p1.u = *(const uint2*)(mh + s1 * 128 + lane * 4);
        __half2 t0 = __hadd2(p0.h[0], p1.h[0]);
        __half2 t1 = __hadd2(p0.h[1], p1.h[1]);
        float2 f0 = __half22float2(t0);
        float2 f1 = __half22float2(t1);
        a0 += f0.x; a1 += f0.y; a2 += f1.x; a3 += f1.y;
    }
    if (i < e) {
        int s0 = __ldg(csr + i);
        union { uint2 u; __half2 h[2]; } p0;
        p0.u = *(const uint2*)(mh + s0 * 128 + lane * 4);
        float2 f;
        f = __half22float2(p0.h[0]); a0 += f.x; a1 += f.y;
        f = __half22float2(p0.h[1]); a2 += f.x; a3 += f.y;
    }

    union { uint2 u; __half2 h[2]; } outp;
    outp.h[0] = __floats2half2_rn(a0, a1);
    outp.h[1] = __floats2half2_rn(a2, a3);
    *(uint2*)(g_aggh + node * 128 + lane * 4) = outp.u;
}

// ---------------------------------------------------------------------------
// Tail: fused mean pool + head (blocks [0,64)) AND re-zero g_deg/g_total for
// the next call (blocks [64, 64+782)). Load-time zero-init covers call 1.
// ---------------------------------------------------------------------------
__global__ void __launch_bounds__(128) k_pool_head_zero(
        const int* __restrict__ batch, const float* __restrict__ b3,
        const float* __restrict__ Wl, const float* __restrict__ bl,
        float* __restrict__ out) {
    if (blockIdx.x >= GRAPHS) {
        int i = (blockIdx.x - GRAPHS) * 128 + threadIdx.x;
        if (i < NODES) g_deg[i] = 0;
        if (i == 0) g_total = 0;
        return;
    }
    __shared__ float hg[DH];
    int g = blockIdx.x, t = threadIdx.x;
    int lo = 0, hi = NODES;
    while (lo < hi) { int m = (lo + hi) >> 1; if (batch[m] < g) lo = m + 1; else hi = m; }
    int s = lo;
    hi = NODES;
    while (lo < hi) { int m = (lo + hi) >> 1; if (batch[m] <= g) lo = m + 1; else hi = m; }
    int e = lo;

    float sum = 0.f;
    for (int n = s; n < e; n++)
        sum = fmaf(__half2float(g_aggh[n * 128 + t]), g_dinv[n], sum);
    int cnt = e - s;
    hg[t] = (cnt > 0) ? (sum / (float)cnt + b3[t]) : 0.f;
    __syncthreads();

    if (t < 32) {
        int lane = t;
        float acc[DOUT];
#pragma unroll
        for (int c = 0; c < DOUT; c++) acc[c] = 0.f;
        for (int k = lane; k < DH; k += 32) {
            float h = hg[k];
#pragma unroll
            for (int c = 0; c < DOUT; c++) acc[c] = fmaf(h, Wl[k * DOUT + c], acc[c]);
        }
#pragma unroll
        for (int off = 16; off > 0; off >>= 1)
#pragma unroll
            for (int c = 0; c < DOUT; c++)
                acc[c] += __shfl_xor_sync(0xFFFFFFFFu, acc[c], off);

        float mx = -1e30f;
#pragma unroll
        for (int c = 0; c < DOUT; c++) { acc[c] += bl[c]; mx = fmaxf(mx, acc[c]); }
        float ssum = 0.f;
#pragma unroll
        for (int c = 0; c < DOUT; c++) { acc[c] = expf(acc[c] - mx); ssum += acc[c]; }
        if (lane < DOUT) out[g * DOUT + lane] = acc[lane] / ssum;
    }
}

// ---------------------------------------------------------------------------
extern "C" void kernel_launch(void* const* d_in, const int* in_sizes, int n_in,
                              void* d_out, int out_size) {
    const float* x     = (const float*)d_in[0];
    const int*   ei    = (const int*)  d_in[1];
    const int*   batch = (const int*)  d_in[2];
    const float* W1 = (const float*)d_in[3];
    const float* b1 = (const float*)d_in[4];
    const float* W2 = (const float*)d_in[5];
    const float* b2 = (const float*)d_in[6];
    const float* W3 = (const float*)d_in[7];
    const float* b3 = (const float*)d_in[8];
    const float* Wl = (const float*)d_in[9];
    const float* bl = (const float*)d_in[10];
    float* out = (float*)d_out;

    const int agg_grid  = (NODES + 1) / 2;
    const int zero_blocks = (NODES + 127) / 128;   // 782

    // idx 0: degree count (g_deg zeroed by tail of previous call / load-init)
    k_count_deg   <<<(EDGES / 4 + 255) / 256, 256>>>(ei);
    // idx 1: CSR alloc + dinv + weight convert
    k_alloc_wconv <<<NB + 24, 256>>>(W1, W2, W3);
    // idx 2: layer-1 GEMM overlapped with CSR fill
    k_gemm1_fill  <<<GEMM_GRID + FILL_GRID, 256>>>(x, ei);
    // idx 3: aggregate layer 1  (ncu capture slot)
    k_aggregate   <<<agg_grid, 64>>>();
    // idx 4..7: layers 2, 3
    k_gemm_tc     <<<GEMM_GRID, 256>>>(1, b1);
    k_aggregate   <<<agg_grid, 64>>>();
    k_gemm_tc     <<<GEMM_GRID, 256>>>(2, b2);
    k_aggregate   <<<agg_grid, 64>>>();
    // idx 8: pool + head + re-zero degree state for next call
    k_pool_head_zero<<<GRAPHS + zero_blocks, 128>>>(batch, b3, Wl, bl, out);
}